// round 3
// baseline (speedup 1.0000x reference)
#include <cuda_runtime.h>
#include <math.h>

#define BATCH   4096
#define NBLK    66
#define XDIM    264      // 66 * 4
#define PHI_H   256
#define PHI_OUT 64
#define RHO_H   256
#define WARPS_PER_BLOCK 8

typedef unsigned long long ull;

// Global scratch: cross-batch max key + transposed pw2 ([c][j] layout).
__device__ unsigned g_maxkey;
__device__ __align__(16) float g_pw2T[PHI_OUT * PHI_H];

// ---- packed f32x2 helpers (sm_103a FFMA2 path, PTX-only) ----
__device__ __forceinline__ ull ffma2(ull a, ull b, ull c) {
    ull d;
    asm("fma.rn.f32x2 %0, %1, %2, %3;" : "=l"(d) : "l"(a), "l"(b), "l"(c));
    return d;
}
__device__ __forceinline__ ull pack2(float lo, float hi) {
    ull v; asm("mov.b64 %0, {%1, %2};" : "=l"(v) : "f"(lo), "f"(hi)); return v;
}
__device__ __forceinline__ float2 unpack2(ull v) {
    float2 r; asm("mov.b64 {%0, %1}, %2;" : "=f"(r.x), "=f"(r.y) : "l"(v)); return r;
}

// Monotonic float->uint key: preserves ordering for all finite floats.
__device__ __forceinline__ unsigned fkey(float f) {
    unsigned b = __float_as_uint(f);
    return (b & 0x80000000u) ? ~b : (b | 0x80000000u);
}
__device__ __forceinline__ float kinv(unsigned k) {
    unsigned b = (k & 0x80000000u) ? (k & 0x7fffffffu) : ~k;
    return __uint_as_float(b);
}

// Init: reset max key + transpose pw2 [j][c] -> g_pw2T [c][j].
__global__ void bn_init_kernel(const float* __restrict__ pw2) {
    const int idx = blockIdx.x * blockDim.x + threadIdx.x;
    if (idx == 0) g_maxkey = 0u;
    if (idx < PHI_OUT * PHI_H) {
        const int c = idx >> 8;          // /256
        const int j = idx & 255;
        g_pw2T[idx] = pw2[j * PHI_OUT + c];
    }
}

__global__ __launch_bounds__(256) void bn_main_kernel(
    const float* __restrict__ x,
    const float* __restrict__ pw1, const float* __restrict__ pb1,
    const float* __restrict__ pb2,
    const float* __restrict__ rw1, const float* __restrict__ rb1,
    const float* __restrict__ rw2, const float* __restrict__ rb2,
    float* __restrict__ out)
{
    // SoA staging of x (component r, block n) -> packed (n, n+1) LDS.64 operands.
    __shared__ __align__(16) float xsT[WARPS_PER_BLOCK][4][NBLK];
    __shared__ __align__(16) float Hs[WARPS_PER_BLOCK][PHI_H];
    __shared__ __align__(16) ull   Xs2[WARPS_PER_BLOCK][PHI_OUT]; // (X_i, X_i) duplicated
    __shared__ unsigned s_max;

    const int tid  = threadIdx.x;
    const int w    = tid >> 5;
    const int lane = tid & 31;
    if (tid == 0) s_max = 0u;

    const int b = blockIdx.x * WARPS_PER_BLOCK + w;   // one batch row per warp

    // ---- stage x row into SoA shared ----
    const float4* xrow4 = reinterpret_cast<const float4*>(x + (size_t)b * XDIM);
    for (int n = lane; n < NBLK; n += 32) {
        const float4 v = xrow4[n];
        xsT[w][0][n] = v.x; xsT[w][1][n] = v.y;
        xsT[w][2][n] = v.z; xsT[w][3][n] = v.w;
    }
    __syncwarp();

    // ---- preload layer-1 weights, broadcast-packed, for 8 units j = lane+32k ----
    ull w1p[4][8], b1p[8];
    #pragma unroll
    for (int k = 0; k < 8; k++) {
        const int j = lane + 32 * k;
        const float bb = __ldg(pb1 + j);
        b1p[k] = pack2(bb, bb);
        #pragma unroll
        for (int r = 0; r < 4; r++) {
            const float ww = __ldg(pw1 + r * PHI_H + j);
            w1p[r][k] = pack2(ww, ww);
        }
    }

    // ---- layer 1 + block-sum, two blocks per iteration (packed over n) ----
    float H[8];
    #pragma unroll
    for (int k = 0; k < 8; k++) H[k] = 0.f;

    #pragma unroll 3
    for (int n = 0; n < NBLK; n += 2) {
        const ull sx = *reinterpret_cast<const ull*>(&xsT[w][0][n]);
        const ull sy = *reinterpret_cast<const ull*>(&xsT[w][1][n]);
        const ull sz = *reinterpret_cast<const ull*>(&xsT[w][2][n]);
        const ull sw = *reinterpret_cast<const ull*>(&xsT[w][3][n]);
        #pragma unroll
        for (int k = 0; k < 8; k++) {
            ull t = b1p[k];
            t = ffma2(w1p[0][k], sx, t);
            t = ffma2(w1p[1][k], sy, t);
            t = ffma2(w1p[2][k], sz, t);
            t = ffma2(w1p[3][k], sw, t);
            const float2 u = unpack2(t);
            H[k] += fmaxf(u.x, 0.f) + fmaxf(u.y, 0.f);
        }
    }

    #pragma unroll
    for (int k = 0; k < 8; k++) Hs[w][lane + 32 * k] = H[k];
    __syncwarp();

    // ---- X = H @ W2 + 66*b2 ; lane owns cols c0=2*lane, c1=2*lane+1 ----
    const int c0 = 2 * lane, c1 = 2 * lane + 1;
    ull acc00 = 0, acc01 = 0, acc10 = 0, acc11 = 0;
    #pragma unroll 4
    for (int j = 0; j < PHI_H; j += 8) {
        const ull h01 = *reinterpret_cast<const ull*>(&Hs[w][j]);
        const ull h23 = *reinterpret_cast<const ull*>(&Hs[w][j + 2]);
        const ull h45 = *reinterpret_cast<const ull*>(&Hs[w][j + 4]);
        const ull h67 = *reinterpret_cast<const ull*>(&Hs[w][j + 6]);
        const ulonglong2 wa = *reinterpret_cast<const ulonglong2*>(&g_pw2T[c0 * PHI_H + j]);
        const ulonglong2 wb = *reinterpret_cast<const ulonglong2*>(&g_pw2T[c0 * PHI_H + j + 4]);
        const ulonglong2 wc = *reinterpret_cast<const ulonglong2*>(&g_pw2T[c1 * PHI_H + j]);
        const ulonglong2 wd = *reinterpret_cast<const ulonglong2*>(&g_pw2T[c1 * PHI_H + j + 4]);
        acc00 = ffma2(h01, wa.x, acc00);
        acc01 = ffma2(h23, wa.y, acc01);
        acc00 = ffma2(h45, wb.x, acc00);
        acc01 = ffma2(h67, wb.y, acc01);
        acc10 = ffma2(h01, wc.x, acc10);
        acc11 = ffma2(h23, wc.y, acc11);
        acc10 = ffma2(h45, wd.x, acc10);
        acc11 = ffma2(h67, wd.y, acc11);
    }
    const float2 bv = *reinterpret_cast<const float2*>(pb2 + c0);
    const float2 p0 = unpack2(acc00), p1 = unpack2(acc01);
    const float2 p2 = unpack2(acc10), p3 = unpack2(acc11);
    const float xv0 = p0.x + p0.y + p1.x + p1.y + 66.f * bv.x;
    const float xv1 = p2.x + p2.y + p3.x + p3.y + 66.f * bv.y;
    Xs2[w][c0] = pack2(xv0, xv0);
    Xs2[w][c1] = pack2(xv1, xv1);
    __syncwarp();

    // ---- rho layer 1: lane owns 8 consecutive units j = 8*lane .. 8*lane+7 ----
    const int j0 = 8 * lane;
    const ulonglong2 rb_a = *reinterpret_cast<const ulonglong2*>(rb1 + j0);
    ull t2_0 = rb_a.x, t2_1 = rb_a.y;
    const ulonglong2 rb_b = *reinterpret_cast<const ulonglong2*>(rb1 + j0 + 4);
    ull t2_2 = rb_b.x, t2_3 = rb_b.y;

    #pragma unroll 8
    for (int i = 0; i < PHI_OUT; i++) {
        const ull xi = Xs2[w][i];  // broadcast, packed (X_i, X_i)
        const ulonglong2 wv0 = *reinterpret_cast<const ulonglong2*>(&rw1[i * RHO_H + j0]);
        const ulonglong2 wv1 = *reinterpret_cast<const ulonglong2*>(&rw1[i * RHO_H + j0 + 4]);
        t2_0 = ffma2(xi, wv0.x, t2_0);
        t2_1 = ffma2(xi, wv0.y, t2_1);
        t2_2 = ffma2(xi, wv1.x, t2_2);
        t2_3 = ffma2(xi, wv1.y, t2_3);
    }

    // ---- relu + rho layer 2 (rw2: [256][2]) ----
    float a0 = 0.f, a1 = 0.f;
    {
        ull tt[4] = { t2_0, t2_1, t2_2, t2_3 };
        #pragma unroll
        for (int p = 0; p < 4; p++) {
            const float2 u = unpack2(tt[p]);
            const float ma = fmaxf(u.x, 0.f);
            const float mb = fmaxf(u.y, 0.f);
            const float4 rv = *reinterpret_cast<const float4*>(&rw2[2 * j0 + 4 * p]);
            a0 = fmaf(ma, rv.x, a0);
            a1 = fmaf(ma, rv.y, a1);
            a0 = fmaf(mb, rv.z, a0);
            a1 = fmaf(mb, rv.w, a1);
        }
    }

    // ---- barrier term over neighbors n = 2..65 (2 per lane) ----
    float bx = 0.f, by = 0.f;
    #pragma unroll
    for (int q = 0; q < 2; q++) {
        const int n = 2 + lane + 32 * q;
        const float px = xsT[w][0][n], py = xsT[w][1][n];
        const float d  = sqrtf(px * px + py * py);
        const float dm = d - 0.15f;
        const float inv = 1.f / (dm * dm);
        bx -= px * inv;
        by -= py * inv;
    }

    // ---- warp butterfly reduce (a0, a1, bx, by) ----
    #pragma unroll
    for (int off = 16; off > 0; off >>= 1) {
        a0 += __shfl_xor_sync(0xffffffff, a0, off);
        a1 += __shfl_xor_sync(0xffffffff, a1, off);
        bx += __shfl_xor_sync(0xffffffff, bx, off);
        by += __shfl_xor_sync(0xffffffff, by, off);
    }

    __syncthreads();  // orders s_max init (thread 0) before atomics below
    if (lane == 0) {
        const float r0 = 2.0f * tanhf(a0 + __ldg(rb2))     + bx;
        const float r1 = 2.0f * tanhf(a1 + __ldg(rb2 + 1)) + by;
        out[2 * b]     = r0;
        out[2 * b + 1] = r1;
        const unsigned k = max(fkey(r0), fkey(r1));
        atomicMax(&s_max, k);
    }
    __syncthreads();
    if (tid == 0) atomicMax(&g_maxkey, s_max);
}

__global__ void bn_scale_kernel(float* __restrict__ out) {
    const int i = blockIdx.x * blockDim.x + threadIdx.x;
    if (i >= BATCH * 2) return;
    const float mx    = kinv(g_maxkey);
    const float scale = 2.0f / mx;
    const float v = out[i];
    out[i] = (scale < 1.0f) ? v * scale : v;
}

extern "C" void kernel_launch(void* const* d_in, const int* in_sizes, int n_in,
                              void* d_out, int out_size)
{
    const float* x   = (const float*)d_in[0];
    const float* pw1 = (const float*)d_in[1];
    const float* pb1 = (const float*)d_in[2];
    const float* pw2 = (const float*)d_in[3];
    const float* pb2 = (const float*)d_in[4];
    const float* rw1 = (const float*)d_in[5];
    const float* rb1 = (const float*)d_in[6];
    const float* rw2 = (const float*)d_in[7];
    const float* rb2 = (const float*)d_in[8];
    float* out = (float*)d_out;

    bn_init_kernel<<<(PHI_OUT * PHI_H + 255) / 256, 256>>>(pw2);
    bn_main_kernel<<<BATCH / WARPS_PER_BLOCK, 256>>>(
        x, pw1, pb1, pb2, rw1, rb1, rw2, rb2, out);
    bn_scale_kernel<<<(BATCH * 2 + 255) / 256, 256>>>(out);
}

// round 4
// speedup vs baseline: 2.0942x; 2.0942x over previous
#include <cuda_runtime.h>
#include <math.h>

#define BATCH   4096
#define NBLK    66
#define XDIM    264      // 66 * 4
#define PHI_H   256
#define PHI_OUT 64
#define RHO_H   256
#define WARPS_PER_BLOCK 4
#define NBLOCKS (BATCH / WARPS_PER_BLOCK)   // 1024

// Global scratch: cross-batch max key + completion counter.
// Self-resetting at end of each run -> kernel is graph-replayable.
__device__ unsigned g_maxkey = 0u;
__device__ unsigned g_done   = 0u;

// Monotonic float->uint key: preserves ordering for all finite floats.
__device__ __forceinline__ unsigned fkey(float f) {
    unsigned b = __float_as_uint(f);
    return (b & 0x80000000u) ? ~b : (b | 0x80000000u);
}
__device__ __forceinline__ float kinv(unsigned k) {
    unsigned b = (k & 0x80000000u) ? (k & 0x7fffffffu) : ~k;
    return __uint_as_float(b);
}

__global__ __launch_bounds__(32 * WARPS_PER_BLOCK) void bn_main_kernel(
    const float* __restrict__ x,
    const float* __restrict__ pw1, const float* __restrict__ pb1,
    const float* __restrict__ pw2, const float* __restrict__ pb2,
    const float* __restrict__ rw1, const float* __restrict__ rb1,
    const float* __restrict__ rw2, const float* __restrict__ rb2,
    float* __restrict__ out)
{
    __shared__ __align__(16) float xs[WARPS_PER_BLOCK][XDIM];
    __shared__ __align__(16) float Hs[WARPS_PER_BLOCK][PHI_H];
    __shared__ __align__(16) float Xs[WARPS_PER_BLOCK][PHI_OUT];
    __shared__ unsigned s_max;
    __shared__ bool     s_last;

    const int tid  = threadIdx.x;
    const int w    = tid >> 5;
    const int lane = tid & 31;
    if (tid == 0) s_max = 0u;

    const int b = blockIdx.x * WARPS_PER_BLOCK + w;   // one batch row per warp

    // ---- stage x row into shared (coalesced float4) ----
    const float4* xrow4 = reinterpret_cast<const float4*>(x + (size_t)b * XDIM);
    float4* xs4 = reinterpret_cast<float4*>(xs[w]);
    for (int n = lane; n < NBLK; n += 32) xs4[n] = xrow4[n];
    __syncwarp();

    // ---- preload layer-1 weights for my 8 hidden units (j = lane + 32k) ----
    float w1r[4][8], b1r[8];
    #pragma unroll
    for (int k = 0; k < 8; k++) {
        const int j = lane + 32 * k;
        b1r[k] = __ldg(pb1 + j);
        #pragma unroll
        for (int r = 0; r < 4; r++) w1r[r][k] = __ldg(pw1 + r * PHI_H + j);
    }

    // ---- layer 1 + block-sum:  H_j = sum_n relu(s_n . w1_j + b1_j) ----
    float H[8];
    #pragma unroll
    for (int k = 0; k < 8; k++) H[k] = 0.f;

    #pragma unroll 2
    for (int n = 0; n < NBLK; n++) {
        const float4 s = xs4[n];
        #pragma unroll
        for (int k = 0; k < 8; k++) {
            float t = b1r[k];
            t = fmaf(w1r[0][k], s.x, t);
            t = fmaf(w1r[1][k], s.y, t);
            t = fmaf(w1r[2][k], s.z, t);
            t = fmaf(w1r[3][k], s.w, t);
            H[k] += fmaxf(t, 0.f);
        }
    }

    #pragma unroll
    for (int k = 0; k < 8; k++) Hs[w][lane + 32 * k] = H[k];
    __syncwarp();

    // ---- X = H @ W2 + 66*b2 : lane owns output cols {2*lane, 2*lane+1} ----
    {
        const float4* hv4 = reinterpret_cast<const float4*>(Hs[w]);
        float x0 = 66.f * __ldg(pb2 + 2 * lane);
        float x1 = 66.f * __ldg(pb2 + 2 * lane + 1);
        #pragma unroll 8
        for (int j4 = 0; j4 < PHI_H / 4; j4++) {
            const float4 h = hv4[j4];
            const int j = 4 * j4;
            const float2 wv0 = __ldg(reinterpret_cast<const float2*>(pw2 + (j    ) * PHI_OUT + 2 * lane));
            const float2 wv1 = __ldg(reinterpret_cast<const float2*>(pw2 + (j + 1) * PHI_OUT + 2 * lane));
            const float2 wv2 = __ldg(reinterpret_cast<const float2*>(pw2 + (j + 2) * PHI_OUT + 2 * lane));
            const float2 wv3 = __ldg(reinterpret_cast<const float2*>(pw2 + (j + 3) * PHI_OUT + 2 * lane));
            x0 = fmaf(h.x, wv0.x, x0);  x1 = fmaf(h.x, wv0.y, x1);
            x0 = fmaf(h.y, wv1.x, x0);  x1 = fmaf(h.y, wv1.y, x1);
            x0 = fmaf(h.z, wv2.x, x0);  x1 = fmaf(h.z, wv2.y, x1);
            x0 = fmaf(h.w, wv3.x, x0);  x1 = fmaf(h.w, wv3.y, x1);
        }
        Xs[w][2 * lane]     = x0;
        Xs[w][2 * lane + 1] = x1;
    }
    __syncwarp();

    // ---- rho layer 1: lane owns 8 consecutive units j = 8*lane..8*lane+7 ----
    const int j0 = 8 * lane;
    float t0, t1, t2, t3, t4, t5, t6, t7;
    {
        const float4 ba = __ldg(reinterpret_cast<const float4*>(rb1 + j0));
        const float4 bb = __ldg(reinterpret_cast<const float4*>(rb1 + j0 + 4));
        t0 = ba.x; t1 = ba.y; t2 = ba.z; t3 = ba.w;
        t4 = bb.x; t5 = bb.y; t6 = bb.z; t7 = bb.w;
    }
    #pragma unroll 8
    for (int i = 0; i < PHI_OUT; i++) {
        const float xi = Xs[w][i];   // LDS broadcast
        const float4 wa = __ldg(reinterpret_cast<const float4*>(rw1 + i * RHO_H + j0));
        const float4 wb = __ldg(reinterpret_cast<const float4*>(rw1 + i * RHO_H + j0 + 4));
        t0 = fmaf(xi, wa.x, t0);  t1 = fmaf(xi, wa.y, t1);
        t2 = fmaf(xi, wa.z, t2);  t3 = fmaf(xi, wa.w, t3);
        t4 = fmaf(xi, wb.x, t4);  t5 = fmaf(xi, wb.y, t5);
        t6 = fmaf(xi, wb.z, t6);  t7 = fmaf(xi, wb.w, t7);
    }

    // ---- relu + rho layer 2 (rw2: [256][2], lane covers rows j0..j0+7) ----
    float a0 = 0.f, a1 = 0.f;
    {
        const float4 r0 = __ldg(reinterpret_cast<const float4*>(rw2 + 2 * j0));
        const float4 r1 = __ldg(reinterpret_cast<const float4*>(rw2 + 2 * j0 + 4));
        const float4 r2 = __ldg(reinterpret_cast<const float4*>(rw2 + 2 * j0 + 8));
        const float4 r3 = __ldg(reinterpret_cast<const float4*>(rw2 + 2 * j0 + 12));
        const float m0 = fmaxf(t0, 0.f), m1 = fmaxf(t1, 0.f);
        const float m2 = fmaxf(t2, 0.f), m3 = fmaxf(t3, 0.f);
        const float m4 = fmaxf(t4, 0.f), m5 = fmaxf(t5, 0.f);
        const float m6 = fmaxf(t6, 0.f), m7 = fmaxf(t7, 0.f);
        a0 = fmaf(m0, r0.x, a0);  a1 = fmaf(m0, r0.y, a1);
        a0 = fmaf(m1, r0.z, a0);  a1 = fmaf(m1, r0.w, a1);
        a0 = fmaf(m2, r1.x, a0);  a1 = fmaf(m2, r1.y, a1);
        a0 = fmaf(m3, r1.z, a0);  a1 = fmaf(m3, r1.w, a1);
        a0 = fmaf(m4, r2.x, a0);  a1 = fmaf(m4, r2.y, a1);
        a0 = fmaf(m5, r2.z, a0);  a1 = fmaf(m5, r2.w, a1);
        a0 = fmaf(m6, r3.x, a0);  a1 = fmaf(m6, r3.y, a1);
        a0 = fmaf(m7, r3.z, a0);  a1 = fmaf(m7, r3.w, a1);
    }

    // ---- barrier term over neighbors n = 2..65 (2 per lane) ----
    float bx = 0.f, by = 0.f;
    #pragma unroll
    for (int q = 0; q < 2; q++) {
        const int n = 2 + lane + 32 * q;
        const float px = xs[w][4 * n], py = xs[w][4 * n + 1];
        const float d  = sqrtf(px * px + py * py);
        const float dm = d - 0.15f;
        const float inv = 1.f / (dm * dm);
        bx -= px * inv;
        by -= py * inv;
    }

    // ---- warp butterfly reduce (a0, a1, bx, by) ----
    #pragma unroll
    for (int off = 16; off > 0; off >>= 1) {
        a0 += __shfl_xor_sync(0xffffffff, a0, off);
        a1 += __shfl_xor_sync(0xffffffff, a1, off);
        bx += __shfl_xor_sync(0xffffffff, bx, off);
        by += __shfl_xor_sync(0xffffffff, by, off);
    }

    __syncthreads();  // orders s_max init (thread 0) before atomics below
    if (lane == 0) {
        const float r0 = 2.0f * tanhf(a0 + __ldg(rb2))     + bx;
        const float r1 = 2.0f * tanhf(a1 + __ldg(rb2 + 1)) + by;
        out[2 * b]     = r0;
        out[2 * b + 1] = r1;
        const unsigned k = max(fkey(r0), fkey(r1));
        atomicMax(&s_max, k);
    }
    __syncthreads();

    // ---- block max -> global; last block applies global rescale ----
    if (tid == 0) {
        atomicMax(&g_maxkey, s_max);
        __threadfence();                       // out[] + g_maxkey visible chip-wide
        const unsigned prev = atomicAdd(&g_done, 1u);
        s_last = (prev == (unsigned)(gridDim.x - 1));
    }
    __syncthreads();

    if (s_last) {
        __threadfence();                       // acquire: see all blocks' writes
        const float mx    = kinv(atomicAdd(&g_maxkey, 0u));
        const float scale = 2.0f / mx;
        if (scale < 1.0f) {
            float4* o4 = reinterpret_cast<float4*>(out);
            for (int i = tid; i < BATCH * 2 / 4; i += blockDim.x) {
                float4 v = o4[i];
                v.x *= scale; v.y *= scale; v.z *= scale; v.w *= scale;
                o4[i] = v;
            }
        }
        __syncthreads();
        if (tid == 0) {                        // reset for next graph replay
            g_maxkey = 0u;
            __threadfence();
            atomicExch(&g_done, 0u);
        }
    }
}

extern "C" void kernel_launch(void* const* d_in, const int* in_sizes, int n_in,
                              void* d_out, int out_size)
{
    const float* x   = (const float*)d_in[0];
    const float* pw1 = (const float*)d_in[1];
    const float* pb1 = (const float*)d_in[2];
    const float* pw2 = (const float*)d_in[3];
    const float* pb2 = (const float*)d_in[4];
    const float* rw1 = (const float*)d_in[5];
    const float* rb1 = (const float*)d_in[6];
    const float* rw2 = (const float*)d_in[7];
    const float* rb2 = (const float*)d_in[8];
    float* out = (float*)d_out;

    bn_main_kernel<<<NBLOCKS, 32 * WARPS_PER_BLOCK>>>(
        x, pw1, pb1, pw2, pb2, rw1, rb1, rw2, rb2, out);
}

// round 5
// speedup vs baseline: 2.4907x; 1.1893x over previous
#include <cuda_runtime.h>
#include <math.h>

#define BATCH   4096
#define NBLK    66
#define XDIM    264      // 66 * 4
#define PHI_H   256
#define PHI_OUT 64
#define RHO_H   256
#define WARPS_PER_BLOCK 4
#define ROWS_PER_WARP   2
#define ROWS_PER_BLOCK  (WARPS_PER_BLOCK * ROWS_PER_WARP)   // 8
#define NBLOCKS (BATCH / ROWS_PER_BLOCK)                    // 512

typedef unsigned long long ull;

// Global scratch: cross-batch max key + completion counter (self-resetting).
__device__ unsigned g_maxkey = 0u;
__device__ unsigned g_done   = 0u;

// ---- packed f32x2 helpers ----
__device__ __forceinline__ ull ffma2(ull a, ull b, ull c) {
    ull d; asm("fma.rn.f32x2 %0, %1, %2, %3;" : "=l"(d) : "l"(a), "l"(b), "l"(c)); return d;
}
__device__ __forceinline__ ull add2(ull a, ull b) {
    ull d; asm("add.rn.f32x2 %0, %1, %2;" : "=l"(d) : "l"(a), "l"(b)); return d;
}
__device__ __forceinline__ ull pack2(float lo, float hi) {
    ull v; asm("mov.b64 %0, {%1, %2};" : "=l"(v) : "f"(lo), "f"(hi)); return v;
}
__device__ __forceinline__ float2 unpack2(ull v) {
    float2 r; asm("mov.b64 {%0, %1}, %2;" : "=f"(r.x), "=f"(r.y) : "l"(v)); return r;
}
__device__ __forceinline__ ull dup2(float v) { return pack2(v, v); }

// Monotonic float->uint key.
__device__ __forceinline__ unsigned fkey(float f) {
    unsigned b = __float_as_uint(f);
    return (b & 0x80000000u) ? ~b : (b | 0x80000000u);
}
__device__ __forceinline__ float kinv(unsigned k) {
    unsigned b = (k & 0x80000000u) ? (k & 0x7fffffffu) : ~k;
    return __uint_as_float(b);
}

__global__ __launch_bounds__(32 * WARPS_PER_BLOCK, 4) void bn_main_kernel(
    const float* __restrict__ x,
    const float* __restrict__ pw1, const float* __restrict__ pb1,
    const float* __restrict__ pw2, const float* __restrict__ pb2,
    const float* __restrict__ rw1, const float* __restrict__ rb1,
    const float* __restrict__ rw2, const float* __restrict__ rb2,
    float* __restrict__ out)
{
    __shared__ __align__(16) float xs[WARPS_PER_BLOCK][ROWS_PER_WARP][XDIM];
    __shared__ __align__(16) float Hs[WARPS_PER_BLOCK][ROWS_PER_WARP][PHI_H];
    __shared__ __align__(16) float Xs[WARPS_PER_BLOCK][ROWS_PER_WARP][PHI_OUT];
    __shared__ unsigned s_max;
    __shared__ bool     s_last;

    const int tid  = threadIdx.x;
    const int w    = tid >> 5;
    const int lane = tid & 31;
    if (tid == 0) s_max = 0u;

    const int bA = blockIdx.x * ROWS_PER_BLOCK + w * ROWS_PER_WARP;  // row A
    const int bB = bA + 1;                                           // row B

    // ---- stage both x rows into shared (coalesced float4) ----
    {
        const float4* rA = reinterpret_cast<const float4*>(x + (size_t)bA * XDIM);
        const float4* rB = reinterpret_cast<const float4*>(x + (size_t)bB * XDIM);
        float4* sA = reinterpret_cast<float4*>(xs[w][0]);
        float4* sB = reinterpret_cast<float4*>(xs[w][1]);
        for (int n = lane; n < NBLK; n += 32) { sA[n] = rA[n]; sB[n] = rB[n]; }
    }
    __syncwarp();

    // ---- preload layer-1 weights packed over unit pairs:
    //      pair k2 covers units (lane + 64*k2, lane + 64*k2 + 32) ----
    ull w1p[4][4], b1p[4];
    #pragma unroll
    for (int k2 = 0; k2 < 4; k2++) {
        const int ja = lane + 64 * k2;
        const int jb = ja + 32;
        b1p[k2] = pack2(__ldg(pb1 + ja), __ldg(pb1 + jb));
        #pragma unroll
        for (int r = 0; r < 4; r++)
            w1p[r][k2] = pack2(__ldg(pw1 + r * PHI_H + ja), __ldg(pw1 + r * PHI_H + jb));
    }

    // ---- layer 1 + block-sum (packed over unit pairs), both rows ----
    #pragma unroll
    for (int row = 0; row < ROWS_PER_WARP; row++) {
        const float4* s4 = reinterpret_cast<const float4*>(xs[w][row]);
        ull H2[4];
        #pragma unroll
        for (int k2 = 0; k2 < 4; k2++) H2[k2] = 0ull;

        #pragma unroll 2
        for (int n = 0; n < NBLK; n++) {
            const float4 s = s4[n];
            const ull sx = dup2(s.x), sy = dup2(s.y), sz = dup2(s.z), sw = dup2(s.w);
            #pragma unroll
            for (int k2 = 0; k2 < 4; k2++) {
                ull t = ffma2(w1p[0][k2], sx, b1p[k2]);
                t = ffma2(w1p[1][k2], sy, t);
                t = ffma2(w1p[2][k2], sz, t);
                t = ffma2(w1p[3][k2], sw, t);
                const float2 u = unpack2(t);
                H2[k2] = add2(H2[k2], pack2(fmaxf(u.x, 0.f), fmaxf(u.y, 0.f)));
            }
        }
        #pragma unroll
        for (int k2 = 0; k2 < 4; k2++) {
            const float2 u = unpack2(H2[k2]);
            Hs[w][row][lane + 64 * k2]      = u.x;
            Hs[w][row][lane + 64 * k2 + 32] = u.y;
        }
    }
    __syncwarp();

    // ---- X = H @ W2 + 66*b2 ; lane owns cols (2*lane, 2*lane+1), packed;
    //      weight loads shared across both rows ----
    {
        const float4* hA4 = reinterpret_cast<const float4*>(Hs[w][0]);
        const float4* hB4 = reinterpret_cast<const float4*>(Hs[w][1]);
        const int c0 = 2 * lane;
        ull accA = 0ull, accB = 0ull;
        #pragma unroll 8
        for (int j4 = 0; j4 < PHI_H / 4; j4++) {
            const float4 hA = hA4[j4];
            const float4 hB = hB4[j4];
            const int j = 4 * j4;
            const float2 v0 = __ldg(reinterpret_cast<const float2*>(pw2 + (j    ) * PHI_OUT + c0));
            const float2 v1 = __ldg(reinterpret_cast<const float2*>(pw2 + (j + 1) * PHI_OUT + c0));
            const float2 v2 = __ldg(reinterpret_cast<const float2*>(pw2 + (j + 2) * PHI_OUT + c0));
            const float2 v3 = __ldg(reinterpret_cast<const float2*>(pw2 + (j + 3) * PHI_OUT + c0));
            const ull w0 = pack2(v0.x, v0.y), w1 = pack2(v1.x, v1.y);
            const ull w2 = pack2(v2.x, v2.y), w3 = pack2(v3.x, v3.y);
            accA = ffma2(dup2(hA.x), w0, accA);
            accA = ffma2(dup2(hA.y), w1, accA);
            accA = ffma2(dup2(hA.z), w2, accA);
            accA = ffma2(dup2(hA.w), w3, accA);
            accB = ffma2(dup2(hB.x), w0, accB);
            accB = ffma2(dup2(hB.y), w1, accB);
            accB = ffma2(dup2(hB.z), w2, accB);
            accB = ffma2(dup2(hB.w), w3, accB);
        }
        const float2 bv = __ldg(reinterpret_cast<const float2*>(pb2 + c0));
        const float2 uA = unpack2(accA), uB = unpack2(accB);
        Xs[w][0][c0]     = uA.x + 66.f * bv.x;
        Xs[w][0][c0 + 1] = uA.y + 66.f * bv.y;
        Xs[w][1][c0]     = uB.x + 66.f * bv.x;
        Xs[w][1][c0 + 1] = uB.y + 66.f * bv.y;
    }
    __syncwarp();

    // ---- rho layer 1: lane owns 8 consecutive units (4 packed pairs);
    //      weight loads shared across both rows ----
    const int j0 = 8 * lane;
    ull tA[4], tB[4];
    {
        const ulonglong2 ra = __ldg(reinterpret_cast<const ulonglong2*>(rb1 + j0));
        const ulonglong2 rb = __ldg(reinterpret_cast<const ulonglong2*>(rb1 + j0 + 4));
        tA[0] = ra.x; tA[1] = ra.y; tA[2] = rb.x; tA[3] = rb.y;
        tB[0] = ra.x; tB[1] = ra.y; tB[2] = rb.x; tB[3] = rb.y;
    }
    #pragma unroll 8
    for (int i = 0; i < PHI_OUT; i++) {
        const ull xA = dup2(Xs[w][0][i]);
        const ull xB = dup2(Xs[w][1][i]);
        const ulonglong2 wa = __ldg(reinterpret_cast<const ulonglong2*>(rw1 + i * RHO_H + j0));
        const ulonglong2 wb = __ldg(reinterpret_cast<const ulonglong2*>(rw1 + i * RHO_H + j0 + 4));
        tA[0] = ffma2(xA, wa.x, tA[0]);  tA[1] = ffma2(xA, wa.y, tA[1]);
        tA[2] = ffma2(xA, wb.x, tA[2]);  tA[3] = ffma2(xA, wb.y, tA[3]);
        tB[0] = ffma2(xB, wa.x, tB[0]);  tB[1] = ffma2(xB, wa.y, tB[1]);
        tB[2] = ffma2(xB, wb.x, tB[2]);  tB[3] = ffma2(xB, wb.y, tB[3]);
    }

    // ---- relu + rho layer 2 ; rw2 rows j0..j0+7, loads shared across rows;
    //      accumulate (a0, a1) packed ----
    ull aA2 = 0ull, aB2 = 0ull;
    {
        const float4 r0 = __ldg(reinterpret_cast<const float4*>(rw2 + 2 * j0));
        const float4 r1 = __ldg(reinterpret_cast<const float4*>(rw2 + 2 * j0 + 4));
        const float4 r2 = __ldg(reinterpret_cast<const float4*>(rw2 + 2 * j0 + 8));
        const float4 r3 = __ldg(reinterpret_cast<const float4*>(rw2 + 2 * j0 + 12));
        const ull q0 = pack2(r0.x, r0.y), q1 = pack2(r0.z, r0.w);
        const ull q2 = pack2(r1.x, r1.y), q3 = pack2(r1.z, r1.w);
        const ull q4 = pack2(r2.x, r2.y), q5 = pack2(r2.z, r2.w);
        const ull q6 = pack2(r3.x, r3.y), q7 = pack2(r3.z, r3.w);
        #pragma unroll
        for (int row = 0; row < ROWS_PER_WARP; row++) {
            const ull* t = (row == 0) ? tA : tB;
            ull acc = 0ull;
            const float2 u0 = unpack2(t[0]), u1 = unpack2(t[1]);
            const float2 u2 = unpack2(t[2]), u3 = unpack2(t[3]);
            acc = ffma2(dup2(fmaxf(u0.x, 0.f)), q0, acc);
            acc = ffma2(dup2(fmaxf(u0.y, 0.f)), q1, acc);
            acc = ffma2(dup2(fmaxf(u1.x, 0.f)), q2, acc);
            acc = ffma2(dup2(fmaxf(u1.y, 0.f)), q3, acc);
            acc = ffma2(dup2(fmaxf(u2.x, 0.f)), q4, acc);
            acc = ffma2(dup2(fmaxf(u2.y, 0.f)), q5, acc);
            acc = ffma2(dup2(fmaxf(u3.x, 0.f)), q6, acc);
            acc = ffma2(dup2(fmaxf(u3.y, 0.f)), q7, acc);
            if (row == 0) aA2 = acc; else aB2 = acc;
        }
    }

    // ---- barrier term over neighbors n = 2..65 (2 per lane per row) ----
    float bxA = 0.f, byA = 0.f, bxB = 0.f, byB = 0.f;
    #pragma unroll
    for (int q = 0; q < 2; q++) {
        const int n = 2 + lane + 32 * q;
        {
            const float px = xs[w][0][4 * n], py = xs[w][0][4 * n + 1];
            const float dm = sqrtf(px * px + py * py) - 0.15f;
            const float inv = 1.f / (dm * dm);
            bxA -= px * inv;  byA -= py * inv;
        }
        {
            const float px = xs[w][1][4 * n], py = xs[w][1][4 * n + 1];
            const float dm = sqrtf(px * px + py * py) - 0.15f;
            const float inv = 1.f / (dm * dm);
            bxB -= px * inv;  byB -= py * inv;
        }
    }

    // ---- warp butterfly reduce ----
    float a0A, a1A, a0B, a1B;
    { const float2 u = unpack2(aA2); a0A = u.x; a1A = u.y; }
    { const float2 u = unpack2(aB2); a0B = u.x; a1B = u.y; }
    #pragma unroll
    for (int off = 16; off > 0; off >>= 1) {
        a0A += __shfl_xor_sync(0xffffffff, a0A, off);
        a1A += __shfl_xor_sync(0xffffffff, a1A, off);
        a0B += __shfl_xor_sync(0xffffffff, a0B, off);
        a1B += __shfl_xor_sync(0xffffffff, a1B, off);
        bxA += __shfl_xor_sync(0xffffffff, bxA, off);
        byA += __shfl_xor_sync(0xffffffff, byA, off);
        bxB += __shfl_xor_sync(0xffffffff, bxB, off);
        byB += __shfl_xor_sync(0xffffffff, byB, off);
    }

    __syncthreads();  // orders s_max init before atomics below
    if (lane == 0) {
        const float rb20 = __ldg(rb2), rb21 = __ldg(rb2 + 1);
        const float rA0 = 2.0f * tanhf(a0A + rb20) + bxA;
        const float rA1 = 2.0f * tanhf(a1A + rb21) + byA;
        const float rB0 = 2.0f * tanhf(a0B + rb20) + bxB;
        const float rB1 = 2.0f * tanhf(a1B + rb21) + byB;
        out[2 * bA]     = rA0;
        out[2 * bA + 1] = rA1;
        out[2 * bB]     = rB0;
        out[2 * bB + 1] = rB1;
        const unsigned k = max(max(fkey(rA0), fkey(rA1)), max(fkey(rB0), fkey(rB1)));
        atomicMax(&s_max, k);
    }
    __syncthreads();

    // ---- block max -> global; last block applies global rescale ----
    if (tid == 0) {
        atomicMax(&g_maxkey, s_max);
        __threadfence();
        const unsigned prev = atomicAdd(&g_done, 1u);
        s_last = (prev == (unsigned)(gridDim.x - 1));
    }
    __syncthreads();

    if (s_last) {
        __threadfence();
        const float mx    = kinv(atomicAdd(&g_maxkey, 0u));
        const float scale = 2.0f / mx;
        if (scale < 1.0f) {
            float4* o4 = reinterpret_cast<float4*>(out);
            for (int i = tid; i < BATCH * 2 / 4; i += blockDim.x) {
                float4 v = o4[i];
                v.x *= scale; v.y *= scale; v.z *= scale; v.w *= scale;
                o4[i] = v;
            }
        }
        __syncthreads();
        if (tid == 0) {
            g_maxkey = 0u;
            __threadfence();
            atomicExch(&g_done, 0u);
        }
    }
}

extern "C" void kernel_launch(void* const* d_in, const int* in_sizes, int n_in,
                              void* d_out, int out_size)
{
    const float* x   = (const float*)d_in[0];
    const float* pw1 = (const float*)d_in[1];
    const float* pb1 = (const float*)d_in[2];
    const float* pw2 = (const float*)d_in[3];
    const float* pb2 = (const float*)d_in[4];
    const float* rw1 = (const float*)d_in[5];
    const float* rb1 = (const float*)d_in[6];
    const float* rw2 = (const float*)d_in[7];
    const float* rb2 = (const float*)d_in[8];
    float* out = (float*)d_out;

    bn_main_kernel<<<NBLOCKS, 32 * WARPS_PER_BLOCK>>>(
        x, pw1, pb1, pw2, pb2, rw1, rb1, rw2, rb2, out);
}